// round 12
// baseline (speedup 1.0000x reference)
#include <cuda_runtime.h>
#include <cstdint>

#define BB 1024
#define TT 256
#define EE 384
#define HH 64

// Scratch (no-allocation rule: __device__ globals).
__device__ float g_q[BB * TT * HH];
__device__ float g_k[BB * TT * HH];   // tf32-rounded, key-pair-permuted within 8-col groups
__device__ float g_v[BB * TT * HH];   // used as g_vt[b][h][key]: transposed, tf32, key-pair-permuted
// W fused+transposed+16-col-permuted+tf32-rounded: [mat*64+n][kp].
__device__ float g_wt[3 * HH * EE];

// ---------------------------------------------------------------------------
// helpers
// ---------------------------------------------------------------------------
__device__ __forceinline__ float ex2f(float x) {
    float y;
    asm("ex2.approx.ftz.f32 %0, %1;" : "=f"(y) : "f"(x));
    return y;
}
__device__ __forceinline__ uint32_t tf32r(float f) {
    uint32_t r;
    asm("cvt.rna.tf32.f32 %0, %1;" : "=r"(r) : "f"(f));
    return r;
}
// m16n8k8 tf32 mma (baseline PTX, works on compute_103).
__device__ __forceinline__ void mma8(float* d, const uint32_t* a, uint32_t b0, uint32_t b1) {
    asm("mma.sync.aligned.m16n8k8.row.col.f32.tf32.tf32.f32 "
        "{%0,%1,%2,%3}, {%4,%5,%6,%7}, {%8,%9}, {%0,%1,%2,%3};"
        : "+f"(d[0]), "+f"(d[1]), "+f"(d[2]), "+f"(d[3])
        : "r"(a[0]), "r"(a[1]), "r"(a[2]), "r"(a[3]), "r"(b0), "r"(b1));
}
__device__ __forceinline__ void cpa16(uint32_t dst, const void* src) {
    asm volatile("cp.async.cg.shared.global [%0], [%1], 16;" :: "r"(dst), "l"(src));
}
__device__ __forceinline__ uint32_t smem_u32(const void* p) {
    uint32_t a;
    asm("{ .reg .u64 t; cvta.to.shared.u64 t, %1; cvt.u32.u64 %0, t; }" : "=r"(a) : "l"(p));
    return a;
}
__device__ __forceinline__ float shflx(float v, int m) {
    return __shfl_xor_sync(0xffffffffu, v, m);
}

// ---------------------------------------------------------------------------
// Kernel 0: build g_wt with 16-col permute: phys q in 16-group -> logical
// k = base + (q>>2) + ((q&3)<<2). One LDS.128 at 16g0+4*tig then yields the
// B fragments of k-chunks 2g0 and 2g0+1. tf32-rounded (rna).
// ---------------------------------------------------------------------------
__global__ void wt_kernel(const float* __restrict__ Wq, const float* __restrict__ Wk,
                          const float* __restrict__ Wv) {
    int idx = blockIdx.x * 256 + threadIdx.x;
    if (idx >= 3 * HH * EE) return;
    int m  = idx / (HH * EE);
    int n  = (idx / EE) & 63;
    int kp = idx % EE;
    int k  = (kp & ~15) + ((kp & 15) >> 2) + ((kp & 3) << 2);
    const float* W = (m == 0) ? Wq : (m == 1) ? Wk : Wv;
    g_wt[idx] = __uint_as_float(tf32r(W[k * HH + n]));
}

// ---------------------------------------------------------------------------
// Kernel 1: QKV projection, mma.sync tf32.
// CTA 128 rows x 192 cols, 8 warps (4M x 2N), warp 32x96. 12 k-chunks of 32,
// double-buffered cp.async. B frags via LDS.128 (dual-chunk permute); x A
// frags tf32-rounded (rna — RZ truncation is biased and fails the 1e-3 gate).
// Epilogue: q fp32; k tf32+pair-permuted; v tf32 -> g_vt [b][h][key], inverse
// pair-permute.
// ---------------------------------------------------------------------------
#define QS_WOFF  20480                      // xs: 128*40*4
#define QS_STAGE (QS_WOFF + 36864)          // + ws: 192*48*4

__device__ __forceinline__ void qkv_load(uint32_t sbase, int stage, int chunk,
                                         const float* __restrict__ x, long long r0) {
    uint32_t xs = sbase + stage * QS_STAGE;
    uint32_t ws = xs + QS_WOFF;
    int tid = threadIdx.x;
#pragma unroll
    for (int i = 0; i < 4; i++) {                 // x: 128 rows x 32 f
        int idx = tid + i * 256;
        int row = idx >> 3, c16 = idx & 7;
        uint32_t doff = (uint32_t)(c16 * 16) ^ (uint32_t)((row & 4) << 2);
        cpa16(xs + row * 160 + doff, x + (r0 + row) * EE + chunk * 32 + c16 * 4);
    }
#pragma unroll
    for (int i = 0; i < 6; i++) {                 // W: 192 rows x 32 f (permuted layout)
        int idx = tid + i * 256;
        int row = idx >> 3, c16 = idx & 7;
        cpa16(ws + row * 192 + c16 * 16, g_wt + row * EE + chunk * 32 + c16 * 4);
    }
}

__global__ void __launch_bounds__(256, 1) qkv_kernel(const float* __restrict__ x)
{
    extern __shared__ __align__(16) char smem[];
    uint32_t sbase = smem_u32(smem);
    int tid = threadIdx.x, wid = tid >> 5, lane = tid & 31;
    int g = lane >> 2, tig = lane & 3;
    int wm = wid >> 1, nh = wid & 1;
    int rb = wm * 32;
    long long r0 = (long long)blockIdx.x * 128;

    float acc[12][2][4];
#pragma unroll
    for (int nt = 0; nt < 12; nt++)
#pragma unroll
        for (int mt = 0; mt < 2; mt++)
#pragma unroll
            for (int i = 0; i < 4; i++) acc[nt][mt][i] = 0.f;

    qkv_load(sbase, 0, 0, x, r0);
    asm volatile("cp.async.commit_group;" ::: "memory");
    qkv_load(sbase, 1, 1, x, r0);
    asm volatile("cp.async.commit_group;" ::: "memory");

    for (int c = 0; c < 12; c++) {
        if (c < 11) asm volatile("cp.async.wait_group 1;" ::: "memory");
        else        asm volatile("cp.async.wait_group 0;" ::: "memory");
        __syncthreads();

        const float* xs = (const float*)(smem + (c & 1) * QS_STAGE);
        const float* ws = (const float*)(smem + (c & 1) * QS_STAGE + QS_WOFF);
#pragma unroll
        for (int g0 = 0; g0 < 2; g0++) {
            // A frags for k-chunks 2g0, 2g0+1 (tf32 rna — unbiased)
            uint32_t A[2][2][4];
#pragma unroll
            for (int mt = 0; mt < 2; mt++) {
                int r_ = rb + mt * 16 + g;
                int sw = r_ & 4;                 // XOR swizzle on float-idx bit2
                int c0 = 16 * g0 + tig;
                A[0][mt][0] = tf32r(xs[r_ * 40 + (c0 ^ sw)]);
                A[0][mt][1] = tf32r(xs[(r_ + 8) * 40 + (c0 ^ sw)]);
                A[0][mt][2] = tf32r(xs[r_ * 40 + ((c0 + 4) ^ sw)]);
                A[0][mt][3] = tf32r(xs[(r_ + 8) * 40 + ((c0 + 4) ^ sw)]);
                A[1][mt][0] = tf32r(xs[r_ * 40 + ((c0 + 8) ^ sw)]);
                A[1][mt][1] = tf32r(xs[(r_ + 8) * 40 + ((c0 + 8) ^ sw)]);
                A[1][mt][2] = tf32r(xs[r_ * 40 + ((c0 + 12) ^ sw)]);
                A[1][mt][3] = tf32r(xs[(r_ + 8) * 40 + ((c0 + 12) ^ sw)]);
            }
#pragma unroll
            for (int nt = 0; nt < 12; nt++) {
                int brow = nh * 96 + nt * 8 + g;
                float4 bv = *(const float4*)&ws[brow * 48 + 16 * g0 + 4 * tig];
                uint32_t b0 = __float_as_uint(bv.x), b1 = __float_as_uint(bv.y);
                uint32_t b2 = __float_as_uint(bv.z), b3 = __float_as_uint(bv.w);
                mma8(acc[nt][0], A[0][0], b0, b1);
                mma8(acc[nt][1], A[0][1], b0, b1);
                mma8(acc[nt][0], A[1][0], b2, b3);
                mma8(acc[nt][1], A[1][1], b2, b3);
            }
        }
        __syncthreads();

        if (c + 2 < 12) {
            qkv_load(sbase, c & 1, c + 2, x, r0);
            asm volatile("cp.async.commit_group;" ::: "memory");
        }
    }

#pragma unroll
    for (int nt = 0; nt < 12; nt++) {
        int gc = nh * 96 + nt * 8;
        int mat = gc >> 6;
#pragma unroll
        for (int mt = 0; mt < 2; mt++) {
            long long row0 = r0 + rb + mt * 16 + g;
            float v0 = acc[nt][mt][0], v1 = acc[nt][mt][1];
            float v2 = acc[nt][mt][2], v3 = acc[nt][mt][3];
            if (mat != 0) {
                v0 = __uint_as_float(tf32r(v0)); v1 = __uint_as_float(tf32r(v1));
                v2 = __uint_as_float(tf32r(v2)); v3 = __uint_as_float(tf32r(v3));
            }
            if (mat == 0) {
                float* op = g_q + (gc & 63) + 2 * tig;
                *(float2*)(op + row0 * HH) = make_float2(v0, v1);
                *(float2*)(op + (row0 + 8) * HH) = make_float2(v2, v3);
            } else if (mat == 1) {
                // key-pair-permute: logical cols (2tig, 2tig+1) -> phys (p0, p0+2)
                int p0 = ((tig & 1) << 2) + (tig >> 1);
                float* o0 = g_k + (gc & 63) + p0;
                o0[row0 * HH] = v0;       o0[row0 * HH + 2] = v1;
                o0[(row0 + 8) * HH] = v2; o0[(row0 + 8) * HH + 2] = v3;
            } else {
                // g_vt[b][h][tok]: transpose + token-pair-permute.
                // Reader maps phys p -> logical (p>>1)+((p&1)<<2); store uses the
                // INVERSE: logical g -> phys 2*(g&3)+(g>>2).
                size_t bofs = (size_t)(r0 >> 8) * (TT * HH);
                int h0 = (gc & 63) + 2 * tig;
                int tok0 = (int)(r0 & 255) + rb + mt * 16;
                int pg = ((g & 3) << 1) + (g >> 2);
                g_v[bofs + (size_t)h0 * 256 + tok0 + pg] = v0;
                g_v[bofs + (size_t)(h0 + 1) * 256 + tok0 + pg] = v1;
                g_v[bofs + (size_t)h0 * 256 + tok0 + 8 + pg] = v2;
                g_v[bofs + (size_t)(h0 + 1) * 256 + tok0 + 8 + pg] = v3;
            }
        }
    }
}

// ---------------------------------------------------------------------------
// Kernel 2: flash attention, mma.sync tf32, 512 thr / 16 warps / CTA=batch.
// Work split (chunk-units of 64 keys; nch(t) = (t+4)>>2):
//   warp w: primary tile w chunks [0, min(nch,2))
//   w<4:    secondary tile w+12 chunks {2,3};  w in 4..7: tile w+4 chunk {2}
// Owners of tiles 8-15 merge the helper partial via pw slots (softmax assoc).
// smem: ks [256][72], vst [64][264] (V^T, key-pair-permuted), pw 16x[16][68].
// ---------------------------------------------------------------------------
#define KVS 72
#define VST 264
#define PST 68
#define ATTN_SMEM ((256 * KVS + 64 * VST + 16 * 16 * PST) * 4)

__device__ __forceinline__ void attn_chunk(
    const float* __restrict__ ks, const float* __restrict__ vst, float* __restrict__ pw,
    const uint32_t (&qf)[8][4], float (&o)[8][4],
    float& mr0, float& mr1, float& l0, float& l1,
    int kc0, int m0, int g, int tig)
{
    float s[8][4];
#pragma unroll
    for (int nt = 0; nt < 8; nt++)
#pragma unroll
        for (int e = 0; e < 4; e++) s[nt][e] = 0.f;
#pragma unroll
    for (int kc = 0; kc < 8; kc++) {
#pragma unroll
        for (int nt = 0; nt < 8; nt++) {
            float2 bv = *(const float2*)(ks + (kc0 + nt * 8 + g) * KVS + kc * 8 + 2 * tig);
            mma8(s[nt], qf[kc], __float_as_uint(bv.x), __float_as_uint(bv.y));
        }
    }
    if (kc0 + 63 > m0) {
        int r0_ = m0 + g, r1_ = m0 + 8 + g;
#pragma unroll
        for (int nt = 0; nt < 8; nt++) {
            int k0_ = kc0 + nt * 8 + 2 * tig;
            s[nt][0] = (k0_     <= r0_) ? s[nt][0] : -INFINITY;
            s[nt][1] = (k0_ + 1 <= r0_) ? s[nt][1] : -INFINITY;
            s[nt][2] = (k0_     <= r1_) ? s[nt][2] : -INFINITY;
            s[nt][3] = (k0_ + 1 <= r1_) ? s[nt][3] : -INFINITY;
        }
    }
    float mx0 = s[0][0], mx1 = s[0][2];
#pragma unroll
    for (int nt = 0; nt < 8; nt++) {
        mx0 = fmaxf(mx0, fmaxf(s[nt][0], s[nt][1]));
        mx1 = fmaxf(mx1, fmaxf(s[nt][2], s[nt][3]));
    }
    mx0 = fmaxf(mx0, shflx(mx0, 1)); mx0 = fmaxf(mx0, shflx(mx0, 2));
    mx1 = fmaxf(mx1, shflx(mx1, 1)); mx1 = fmaxf(mx1, shflx(mx1, 2));
    float mn0 = fmaxf(mr0, mx0), mn1 = fmaxf(mr1, mx1);
    float c0 = ex2f(mr0 - mn0), c1 = ex2f(mr1 - mn1);
    mr0 = mn0; mr1 = mn1;
    float p0 = 0.f, p1 = 0.f;
#pragma unroll
    for (int nt = 0; nt < 8; nt++) {
        s[nt][0] = ex2f(s[nt][0] - mr0);
        s[nt][1] = ex2f(s[nt][1] - mr0);
        s[nt][2] = ex2f(s[nt][2] - mr1);
        s[nt][3] = ex2f(s[nt][3] - mr1);
        p0 += s[nt][0] + s[nt][1];
        p1 += s[nt][2] + s[nt][3];
    }
    p0 += shflx(p0, 1); p0 += shflx(p0, 2);
    p1 += shflx(p1, 1); p1 += shflx(p1, 2);
    l0 = l0 * c0 + p0;
    l1 = l1 * c1 + p1;
#pragma unroll
    for (int nt = 0; nt < 8; nt++) {
        o[nt][0] *= c0; o[nt][1] *= c0;
        o[nt][2] *= c1; o[nt][3] *= c1;
    }
    __syncwarp();
#pragma unroll
    for (int nt = 0; nt < 8; nt++) {
        int cb = nt * 8 + 2 * tig;
        *(float2*)&pw[g * PST + cb] =
            make_float2(__uint_as_float(tf32r(s[nt][0])), __uint_as_float(tf32r(s[nt][1])));
        *(float2*)&pw[(8 + g) * PST + cb] =
            make_float2(__uint_as_float(tf32r(s[nt][2])), __uint_as_float(tf32r(s[nt][3])));
    }
    __syncwarp();
#pragma unroll
    for (int kc2 = 0; kc2 < 8; kc2++) {
        uint32_t pa[4];
        pa[0] = __float_as_uint(pw[g * PST + kc2 * 8 + tig]);
        pa[1] = __float_as_uint(pw[(8 + g) * PST + kc2 * 8 + tig]);
        pa[2] = __float_as_uint(pw[g * PST + kc2 * 8 + tig + 4]);
        pa[3] = __float_as_uint(pw[(8 + g) * PST + kc2 * 8 + tig + 4]);
#pragma unroll
        for (int nt2 = 0; nt2 < 8; nt2++) {
            float2 bv = *(const float2*)(vst + (nt2 * 8 + g) * VST + kc0 + kc2 * 8 + 2 * tig);
            mma8(o[nt2], pa, __float_as_uint(bv.x), __float_as_uint(bv.y));
        }
    }
    __syncwarp();
}

__device__ __forceinline__ void load_qf(uint32_t (&qf)[8][4], const float* __restrict__ qg,
                                        int m0, int g, int tig) {
    const float scl = 0.125f * 1.44269504089f;   // 1/sqrt(64) * log2(e)
#pragma unroll
    for (int kc = 0; kc < 8; kc++) {
        qf[kc][0] = tf32r(scl * qg[(m0 + g) * 64 + kc * 8 + tig]);
        qf[kc][1] = tf32r(scl * qg[(m0 + 8 + g) * 64 + kc * 8 + tig]);
        qf[kc][2] = tf32r(scl * qg[(m0 + g) * 64 + kc * 8 + tig + 4]);
        qf[kc][3] = tf32r(scl * qg[(m0 + 8 + g) * 64 + kc * 8 + tig + 4]);
    }
}

__global__ void __launch_bounds__(512, 1) attn_kernel(float* __restrict__ out)
{
    extern __shared__ __align__(16) float sm[];
    float* ks  = sm;                       // [256][72]
    float* vst = sm + 256 * KVS;           // [64][264]
    float* pwb = vst + 64 * VST;           // 16 x [16][68]
    int b = blockIdx.x;
    int tid = threadIdx.x, w = tid >> 5, lane = tid & 31;
    int g = lane >> 2, tig = lane & 3;
    float* pw = pwb + w * (16 * PST);

    {
        uint32_t ksu = smem_u32(ks);
        uint32_t vsu = smem_u32(vst);
        const float* kg = g_k + (size_t)b * TT * HH;
        const float* vg = g_v + (size_t)b * TT * HH;   // [64][256]
#pragma unroll
        for (int i = 0; i < 8; i++) {
            int idx = tid + i * 512;       // 0..4095
            int key = idx >> 4, h4 = idx & 15;
            cpa16(ksu + (uint32_t)(key * KVS + h4 * 4) * 4, kg + key * 64 + h4 * 4);
            int h = idx >> 6, k4 = idx & 63;
            cpa16(vsu + (uint32_t)(h * VST + k4 * 4) * 4, vg + h * 256 + k4 * 4);
        }
        asm volatile("cp.async.commit_group;" ::: "memory");
    }

    const float* qg = g_q + (size_t)b * TT * HH;
    uint32_t qf[8][4];
    int m0 = w * 16;
    load_qf(qf, qg, m0, g, tig);

    asm volatile("cp.async.wait_group 0;" ::: "memory");
    __syncthreads();

    float o[8][4];
#pragma unroll
    for (int nt = 0; nt < 8; nt++)
#pragma unroll
        for (int e = 0; e < 4; e++) o[nt][e] = 0.f;
    float mr0 = -INFINITY, mr1 = -INFINITY, l0 = 0.f, l1 = 0.f;

    int nch = (w + 4) >> 2;
    int prim = nch < 2 ? nch : 2;
    for (int ci = 0; ci < prim; ci++)
        attn_chunk(ks, vst, pw, qf, o, mr0, mr1, l0, l1, ci * 64, m0, g, tig);

    if (w < 8) {
        // tiles 0-7 complete: finalize + store now
        float inv0 = 1.0f / l0, inv1 = 1.0f / l1;
        float* ob = out + ((size_t)b * TT + m0) * HH;
#pragma unroll
        for (int nt = 0; nt < 8; nt++) {
            int cb = nt * 8 + 2 * tig;
            *(float2*)(ob + g * 64 + cb) = make_float2(o[nt][0] * inv0, o[nt][1] * inv0);
            *(float2*)(ob + (8 + g) * 64 + cb) = make_float2(o[nt][2] * inv1, o[nt][3] * inv1);
        }
        // secondary (helper) work
        int t2 = (w < 4) ? (w + 12) : (w + 4);
        int cend = (w < 4) ? 4 : 3;
        int m02 = t2 * 16;
        load_qf(qf, qg, m02, g, tig);
#pragma unroll
        for (int nt = 0; nt < 8; nt++)
#pragma unroll
            for (int e = 0; e < 4; e++) o[nt][e] = 0.f;
        mr0 = -INFINITY; mr1 = -INFINITY; l0 = 0.f; l1 = 0.f;
        for (int ci = 2; ci < cend; ci++)
            attn_chunk(ks, vst, pw, qf, o, mr0, mr1, l0, l1, ci * 64, m02, g, tig);
        // write partial (unnormalized O + stats) to own pw slot
        __syncwarp();
#pragma unroll
        for (int nt = 0; nt < 8; nt++) {
            int cb = nt * 8 + 2 * tig;
            *(float2*)&pw[g * PST + cb] = make_float2(o[nt][0], o[nt][1]);
            *(float2*)&pw[(8 + g) * PST + cb] = make_float2(o[nt][2], o[nt][3]);
        }
        if (tig == 0) {
            pw[g * PST + 64] = mr0;       pw[g * PST + 65] = l0;
            pw[(8 + g) * PST + 64] = mr1; pw[(8 + g) * PST + 65] = l1;
        }
    }
    __syncthreads();
    if (w >= 8) {
        int h = (w < 12) ? (w - 4) : (w - 12);
        const float* ph = pwb + h * (16 * PST);
        float mh0 = ph[g * PST + 64], lh0 = ph[g * PST + 65];
        float mh1 = ph[(8 + g) * PST + 64], lh1 = ph[(8 + g) * PST + 65];
        float M0 = fmaxf(mr0, mh0), M1 = fmaxf(mr1, mh1);
        float a0 = ex2f(mr0 - M0), b0_ = ex2f(mh0 - M0);
        float a1 = ex2f(mr1 - M1), b1_ = ex2f(mh1 - M1);
        l0 = l0 * a0 + lh0 * b0_;
        l1 = l1 * a1 + lh1 * b1_;
#pragma unroll
        for (int nt = 0; nt < 8; nt++) {
            int cb = nt * 8 + 2 * tig;
            float2 h0v = *(const float2*)&ph[g * PST + cb];
            float2 h1v = *(const float2*)&ph[(8 + g) * PST + cb];
            o[nt][0] = o[nt][0] * a0 + h0v.x * b0_;
            o[nt][1] = o[nt][1] * a0 + h0v.y * b0_;
            o[nt][2] = o[nt][2] * a1 + h1v.x * b1_;
            o[nt][3] = o[nt][3] * a1 + h1v.y * b1_;
        }
        float inv0 = 1.0f / l0, inv1 = 1.0f / l1;
        float* ob = out + ((size_t)b * TT + m0) * HH;
#pragma unroll
        for (int nt = 0; nt < 8; nt++) {
            int cb = nt * 8 + 2 * tig;
            *(float2*)(ob + g * 64 + cb) = make_float2(o[nt][0] * inv0, o[nt][1] * inv0);
            *(float2*)(ob + (8 + g) * 64 + cb) = make_float2(o[nt][2] * inv1, o[nt][3] * inv1);
        }
    }
}

extern "C" void kernel_launch(void* const* d_in, const int* in_sizes, int n_in,
                              void* d_out, int out_size)
{
    (void)in_sizes; (void)n_in; (void)out_size;
    const float* x  = (const float*)d_in[0];
    const float* Wq = (const float*)d_in[1];
    const float* Wk = (const float*)d_in[2];
    const float* Wv = (const float*)d_in[3];
    float* out = (float*)d_out;

    const int qkv_smem = 2 * QS_STAGE;                        // ~112 KB
    cudaFuncSetAttribute(qkv_kernel, cudaFuncAttributeMaxDynamicSharedMemorySize, qkv_smem);
    cudaFuncSetAttribute(attn_kernel, cudaFuncAttributeMaxDynamicSharedMemorySize, ATTN_SMEM);

    wt_kernel<<<(3 * HH * EE + 255) / 256, 256>>>(Wq, Wk, Wv);
    qkv_kernel<<<(BB * TT) / 128, 256, qkv_smem>>>(x);
    attn_kernel<<<BB, 512, ATTN_SMEM>>>(out);
}

// round 13
// speedup vs baseline: 1.0565x; 1.0565x over previous
#include <cuda_runtime.h>
#include <cstdint>

#define BB 1024
#define TT 256
#define EE 384
#define HH 64

// Scratch (no-allocation rule: __device__ globals).
__device__ float g_q[BB * TT * HH];   // PRE-SCALED by 1/sqrt(H)*log2(e), tf32-rounded
__device__ float g_k[BB * TT * HH];   // tf32-rounded, key-pair-permuted within 8-col groups
__device__ float g_v[BB * TT * HH];   // g_vt[b][h][key]: transposed, tf32, key-pair-permuted
// W fused+transposed+16-col-permuted+tf32-rounded: [mat*64+n][kp].
__device__ float g_wt[3 * HH * EE];

// ---------------------------------------------------------------------------
// helpers
// ---------------------------------------------------------------------------
__device__ __forceinline__ float ex2f(float x) {
    float y;
    asm("ex2.approx.ftz.f32 %0, %1;" : "=f"(y) : "f"(x));
    return y;
}
__device__ __forceinline__ uint32_t tf32r(float f) {
    uint32_t r;
    asm("cvt.rna.tf32.f32 %0, %1;" : "=r"(r) : "f"(f));
    return r;
}
// m16n8k8 tf32 mma (baseline PTX, works on compute_103).
__device__ __forceinline__ void mma8(float* d, const uint32_t* a, uint32_t b0, uint32_t b1) {
    asm("mma.sync.aligned.m16n8k8.row.col.f32.tf32.tf32.f32 "
        "{%0,%1,%2,%3}, {%4,%5,%6,%7}, {%8,%9}, {%0,%1,%2,%3};"
        : "+f"(d[0]), "+f"(d[1]), "+f"(d[2]), "+f"(d[3])
        : "r"(a[0]), "r"(a[1]), "r"(a[2]), "r"(a[3]), "r"(b0), "r"(b1));
}
__device__ __forceinline__ void cpa16(uint32_t dst, const void* src) {
    asm volatile("cp.async.cg.shared.global [%0], [%1], 16;" :: "r"(dst), "l"(src));
}
__device__ __forceinline__ uint32_t smem_u32(const void* p) {
    uint32_t a;
    asm("{ .reg .u64 t; cvta.to.shared.u64 t, %1; cvt.u32.u64 %0, t; }" : "=r"(a) : "l"(p));
    return a;
}
__device__ __forceinline__ float shflx(float v, int m) {
    return __shfl_xor_sync(0xffffffffu, v, m);
}

// ---------------------------------------------------------------------------
// Kernel 0: build g_wt with 16-col permute: phys q in 16-group -> logical
// k = base + (q>>2) + ((q&3)<<2). One LDS.128 at 16g0+4*tig then yields the
// B fragments of k-chunks 2g0 and 2g0+1. tf32-rounded (rna).
// ---------------------------------------------------------------------------
__global__ void wt_kernel(const float* __restrict__ Wq, const float* __restrict__ Wk,
                          const float* __restrict__ Wv) {
    int idx = blockIdx.x * 256 + threadIdx.x;
    if (idx >= 3 * HH * EE) return;
    int m  = idx / (HH * EE);
    int n  = (idx / EE) & 63;
    int kp = idx % EE;
    int k  = (kp & ~15) + ((kp & 15) >> 2) + ((kp & 3) << 2);
    const float* W = (m == 0) ? Wq : (m == 1) ? Wk : Wv;
    g_wt[idx] = __uint_as_float(tf32r(W[k * HH + n]));
}

// ---------------------------------------------------------------------------
// Kernel 1: QKV projection, mma.sync tf32.
// CTA 128 rows x 192 cols, 8 warps (4M x 2N), warp 32x96. 12 k-chunks of 32,
// double-buffered cp.async. B frags via LDS.128 (dual-chunk permute); x A
// frags tf32-rounded (rna). Epilogue: q pre-scaled+tf32; k tf32+pair-permuted;
// v tf32 -> g_vt [b][h][key], inverse pair-permute.
// ---------------------------------------------------------------------------
#define QS_WOFF  20480                      // xs: 128*40*4
#define QS_STAGE (QS_WOFF + 36864)          // + ws: 192*48*4

__device__ __forceinline__ void qkv_load(uint32_t sbase, int stage, int chunk,
                                         const float* __restrict__ x, long long r0) {
    uint32_t xs = sbase + stage * QS_STAGE;
    uint32_t ws = xs + QS_WOFF;
    int tid = threadIdx.x;
#pragma unroll
    for (int i = 0; i < 4; i++) {                 // x: 128 rows x 32 f
        int idx = tid + i * 256;
        int row = idx >> 3, c16 = idx & 7;
        uint32_t doff = (uint32_t)(c16 * 16) ^ (uint32_t)((row & 4) << 2);
        cpa16(xs + row * 160 + doff, x + (r0 + row) * EE + chunk * 32 + c16 * 4);
    }
#pragma unroll
    for (int i = 0; i < 6; i++) {                 // W: 192 rows x 32 f (permuted layout)
        int idx = tid + i * 256;
        int row = idx >> 3, c16 = idx & 7;
        cpa16(ws + row * 192 + c16 * 16, g_wt + row * EE + chunk * 32 + c16 * 4);
    }
}

__global__ void __launch_bounds__(256, 1) qkv_kernel(const float* __restrict__ x)
{
    extern __shared__ __align__(16) char smem[];
    uint32_t sbase = smem_u32(smem);
    int tid = threadIdx.x, wid = tid >> 5, lane = tid & 31;
    int g = lane >> 2, tig = lane & 3;
    int wm = wid >> 1, nh = wid & 1;
    int rb = wm * 32;
    long long r0 = (long long)blockIdx.x * 128;

    float acc[12][2][4];
#pragma unroll
    for (int nt = 0; nt < 12; nt++)
#pragma unroll
        for (int mt = 0; mt < 2; mt++)
#pragma unroll
            for (int i = 0; i < 4; i++) acc[nt][mt][i] = 0.f;

    qkv_load(sbase, 0, 0, x, r0);
    asm volatile("cp.async.commit_group;" ::: "memory");
    qkv_load(sbase, 1, 1, x, r0);
    asm volatile("cp.async.commit_group;" ::: "memory");

    for (int c = 0; c < 12; c++) {
        if (c < 11) asm volatile("cp.async.wait_group 1;" ::: "memory");
        else        asm volatile("cp.async.wait_group 0;" ::: "memory");
        __syncthreads();

        const float* xs = (const float*)(smem + (c & 1) * QS_STAGE);
        const float* ws = (const float*)(smem + (c & 1) * QS_STAGE + QS_WOFF);
#pragma unroll
        for (int g0 = 0; g0 < 2; g0++) {
            // A frags for k-chunks 2g0, 2g0+1 (tf32 rna — unbiased)
            uint32_t A[2][2][4];
#pragma unroll
            for (int mt = 0; mt < 2; mt++) {
                int r_ = rb + mt * 16 + g;
                int sw = r_ & 4;                 // XOR swizzle on float-idx bit2
                int c0 = 16 * g0 + tig;
                A[0][mt][0] = tf32r(xs[r_ * 40 + (c0 ^ sw)]);
                A[0][mt][1] = tf32r(xs[(r_ + 8) * 40 + (c0 ^ sw)]);
                A[0][mt][2] = tf32r(xs[r_ * 40 + ((c0 + 4) ^ sw)]);
                A[0][mt][3] = tf32r(xs[(r_ + 8) * 40 + ((c0 + 4) ^ sw)]);
                A[1][mt][0] = tf32r(xs[r_ * 40 + ((c0 + 8) ^ sw)]);
                A[1][mt][1] = tf32r(xs[(r_ + 8) * 40 + ((c0 + 8) ^ sw)]);
                A[1][mt][2] = tf32r(xs[r_ * 40 + ((c0 + 12) ^ sw)]);
                A[1][mt][3] = tf32r(xs[(r_ + 8) * 40 + ((c0 + 12) ^ sw)]);
            }
#pragma unroll
            for (int nt = 0; nt < 12; nt++) {
                int brow = nh * 96 + nt * 8 + g;
                float4 bv = *(const float4*)&ws[brow * 48 + 16 * g0 + 4 * tig];
                uint32_t b0 = __float_as_uint(bv.x), b1 = __float_as_uint(bv.y);
                uint32_t b2 = __float_as_uint(bv.z), b3 = __float_as_uint(bv.w);
                mma8(acc[nt][0], A[0][0], b0, b1);
                mma8(acc[nt][1], A[0][1], b0, b1);
                mma8(acc[nt][0], A[1][0], b2, b3);
                mma8(acc[nt][1], A[1][1], b2, b3);
            }
        }
        __syncthreads();

        if (c + 2 < 12) {
            qkv_load(sbase, c & 1, c + 2, x, r0);
            asm volatile("cp.async.commit_group;" ::: "memory");
        }
    }

    const float scl = 0.125f * 1.44269504089f;   // folded into q here
#pragma unroll
    for (int nt = 0; nt < 12; nt++) {
        int gc = nh * 96 + nt * 8;
        int mat = gc >> 6;
#pragma unroll
        for (int mt = 0; mt < 2; mt++) {
            long long row0 = r0 + rb + mt * 16 + g;
            float v0 = acc[nt][mt][0], v1 = acc[nt][mt][1];
            float v2 = acc[nt][mt][2], v3 = acc[nt][mt][3];
            if (mat == 0) {
                // q: pre-scale + tf32-round (attn consumes raw bits as A frags)
                v0 = __uint_as_float(tf32r(scl * v0));
                v1 = __uint_as_float(tf32r(scl * v1));
                v2 = __uint_as_float(tf32r(scl * v2));
                v3 = __uint_as_float(tf32r(scl * v3));
                float* op = g_q + (gc & 63) + 2 * tig;
                *(float2*)(op + row0 * HH) = make_float2(v0, v1);
                *(float2*)(op + (row0 + 8) * HH) = make_float2(v2, v3);
            } else {
                v0 = __uint_as_float(tf32r(v0)); v1 = __uint_as_float(tf32r(v1));
                v2 = __uint_as_float(tf32r(v2)); v3 = __uint_as_float(tf32r(v3));
                if (mat == 1) {
                    // key-pair-permute: logical cols (2tig, 2tig+1) -> phys (p0, p0+2)
                    int p0 = ((tig & 1) << 2) + (tig >> 1);
                    float* o0 = g_k + (gc & 63) + p0;
                    o0[row0 * HH] = v0;       o0[row0 * HH + 2] = v1;
                    o0[(row0 + 8) * HH] = v2; o0[(row0 + 8) * HH + 2] = v3;
                } else {
                    // g_vt[b][h][tok]: transpose + token-pair-permute.
                    // Reader maps phys p -> logical (p>>1)+((p&1)<<2); store is the
                    // INVERSE: logical g -> phys 2*(g&3)+(g>>2).
                    size_t bofs = (size_t)(r0 >> 8) * (TT * HH);
                    int h0 = (gc & 63) + 2 * tig;
                    int tok0 = (int)(r0 & 255) + rb + mt * 16;
                    int pg = ((g & 3) << 1) + (g >> 2);
                    g_v[bofs + (size_t)h0 * 256 + tok0 + pg] = v0;
                    g_v[bofs + (size_t)(h0 + 1) * 256 + tok0 + pg] = v1;
                    g_v[bofs + (size_t)h0 * 256 + tok0 + 8 + pg] = v2;
                    g_v[bofs + (size_t)(h0 + 1) * 256 + tok0 + 8 + pg] = v3;
                }
            }
        }
    }
}

// ---------------------------------------------------------------------------
// Kernel 2: flash attention, mma.sync tf32, 512 thr / 16 warps / CTA=batch.
// Warp w owns tile w; nch(w) = (w+4)>>2; SMSP s gets tiles {s,s+4,s+8,s+12}
// = 10 chunk-units (balanced). NO resident Q fragments: q is pre-scaled tf32
// in global; A frags loaded per chunk via LDG (L1-hot) -> per-thread live
// state ~100 regs -> no spills at 512 threads (the R8/R12 killer).
// smem: ks [256][72], vst [64][264] (V^T), pw 16x[16][68]. ~206 KB.
// ---------------------------------------------------------------------------
#define KVS 72
#define VST 264
#define PST 68
#define ATTN_SMEM ((256 * KVS + 64 * VST + 16 * 16 * PST) * 4)

__device__ __forceinline__ void attn_chunk(
    const float* __restrict__ ks, const float* __restrict__ vst, float* __restrict__ pw,
    const float* __restrict__ qg, float (&o)[8][4],
    float& mr0, float& mr1, float& l0, float& l1,
    int kc0, int m0, int g, int tig)
{
    float s[8][4];
#pragma unroll
    for (int nt = 0; nt < 8; nt++)
#pragma unroll
        for (int e = 0; e < 4; e++) s[nt][e] = 0.f;
#pragma unroll
    for (int kc = 0; kc < 8; kc++) {
        uint32_t qa[4];
        const float* q0 = qg + (m0 + g) * 64 + kc * 8;
        const float* q1 = qg + (m0 + 8 + g) * 64 + kc * 8;
        qa[0] = __float_as_uint(q0[tig]);
        qa[1] = __float_as_uint(q1[tig]);
        qa[2] = __float_as_uint(q0[tig + 4]);
        qa[3] = __float_as_uint(q1[tig + 4]);
#pragma unroll
        for (int nt = 0; nt < 8; nt++) {
            float2 bv = *(const float2*)(ks + (kc0 + nt * 8 + g) * KVS + kc * 8 + 2 * tig);
            mma8(s[nt], qa, __float_as_uint(bv.x), __float_as_uint(bv.y));
        }
    }
    if (kc0 + 63 > m0) {
        int r0_ = m0 + g, r1_ = m0 + 8 + g;
#pragma unroll
        for (int nt = 0; nt < 8; nt++) {
            int k0_ = kc0 + nt * 8 + 2 * tig;
            s[nt][0] = (k0_     <= r0_) ? s[nt][0] : -INFINITY;
            s[nt][1] = (k0_ + 1 <= r0_) ? s[nt][1] : -INFINITY;
            s[nt][2] = (k0_     <= r1_) ? s[nt][2] : -INFINITY;
            s[nt][3] = (k0_ + 1 <= r1_) ? s[nt][3] : -INFINITY;
        }
    }
    float mx0 = s[0][0], mx1 = s[0][2];
#pragma unroll
    for (int nt = 0; nt < 8; nt++) {
        mx0 = fmaxf(mx0, fmaxf(s[nt][0], s[nt][1]));
        mx1 = fmaxf(mx1, fmaxf(s[nt][2], s[nt][3]));
    }
    mx0 = fmaxf(mx0, shflx(mx0, 1)); mx0 = fmaxf(mx0, shflx(mx0, 2));
    mx1 = fmaxf(mx1, shflx(mx1, 1)); mx1 = fmaxf(mx1, shflx(mx1, 2));
    float mn0 = fmaxf(mr0, mx0), mn1 = fmaxf(mr1, mx1);
    float c0 = ex2f(mr0 - mn0), c1 = ex2f(mr1 - mn1);
    mr0 = mn0; mr1 = mn1;
    float p0 = 0.f, p1 = 0.f;
#pragma unroll
    for (int nt = 0; nt < 8; nt++) {
        s[nt][0] = ex2f(s[nt][0] - mr0);
        s[nt][1] = ex2f(s[nt][1] - mr0);
        s[nt][2] = ex2f(s[nt][2] - mr1);
        s[nt][3] = ex2f(s[nt][3] - mr1);
        p0 += s[nt][0] + s[nt][1];
        p1 += s[nt][2] + s[nt][3];
    }
    p0 += shflx(p0, 1); p0 += shflx(p0, 2);
    p1 += shflx(p1, 1); p1 += shflx(p1, 2);
    l0 = l0 * c0 + p0;
    l1 = l1 * c1 + p1;
#pragma unroll
    for (int nt = 0; nt < 8; nt++) {
        o[nt][0] *= c0; o[nt][1] *= c0;
        o[nt][2] *= c1; o[nt][3] *= c1;
    }
    __syncwarp();
#pragma unroll
    for (int nt = 0; nt < 8; nt++) {
        int cb = nt * 8 + 2 * tig;
        *(float2*)&pw[g * PST + cb] =
            make_float2(__uint_as_float(tf32r(s[nt][0])), __uint_as_float(tf32r(s[nt][1])));
        *(float2*)&pw[(8 + g) * PST + cb] =
            make_float2(__uint_as_float(tf32r(s[nt][2])), __uint_as_float(tf32r(s[nt][3])));
    }
    __syncwarp();
#pragma unroll
    for (int kc2 = 0; kc2 < 8; kc2++) {
        uint32_t pa[4];
        pa[0] = __float_as_uint(pw[g * PST + kc2 * 8 + tig]);
        pa[1] = __float_as_uint(pw[(8 + g) * PST + kc2 * 8 + tig]);
        pa[2] = __float_as_uint(pw[g * PST + kc2 * 8 + tig + 4]);
        pa[3] = __float_as_uint(pw[(8 + g) * PST + kc2 * 8 + tig + 4]);
#pragma unroll
        for (int nt2 = 0; nt2 < 8; nt2++) {
            float2 bv = *(const float2*)(vst + (nt2 * 8 + g) * VST + kc0 + kc2 * 8 + 2 * tig);
            mma8(o[nt2], pa, __float_as_uint(bv.x), __float_as_uint(bv.y));
        }
    }
    __syncwarp();
}

__global__ void __launch_bounds__(512, 1) attn_kernel(float* __restrict__ out)
{
    extern __shared__ __align__(16) float sm[];
    float* ks  = sm;                       // [256][72]
    float* vst = sm + 256 * KVS;           // [64][264]
    float* pwb = vst + 64 * VST;           // 16 x [16][68]
    int b = blockIdx.x;
    int tid = threadIdx.x, w = tid >> 5, lane = tid & 31;
    int g = lane >> 2, tig = lane & 3;
    float* pw = pwb + w * (16 * PST);

    {
        uint32_t ksu = smem_u32(ks);
        uint32_t vsu = smem_u32(vst);
        const float* kg = g_k + (size_t)b * TT * HH;
        const float* vg = g_v + (size_t)b * TT * HH;   // [64][256]
#pragma unroll
        for (int i = 0; i < 8; i++) {
            int idx = tid + i * 512;       // 0..4095
            int key = idx >> 4, h4 = idx & 15;
            cpa16(ksu + (uint32_t)(key * KVS + h4 * 4) * 4, kg + key * 64 + h4 * 4);
            int h = idx >> 6, k4 = idx & 63;
            cpa16(vsu + (uint32_t)(h * VST + k4 * 4) * 4, vg + h * 256 + k4 * 4);
        }
        asm volatile("cp.async.commit_group;" ::: "memory");
    }

    const float* qg = g_q + (size_t)b * TT * HH;   // pre-scaled, tf32
    int m0 = w * 16;

    asm volatile("cp.async.wait_group 0;" ::: "memory");
    __syncthreads();

    float o[8][4];
#pragma unroll
    for (int nt = 0; nt < 8; nt++)
#pragma unroll
        for (int e = 0; e < 4; e++) o[nt][e] = 0.f;
    float mr0 = -INFINITY, mr1 = -INFINITY, l0 = 0.f, l1 = 0.f;

    int nch = (w + 4) >> 2;
    for (int ci = 0; ci < nch; ci++)
        attn_chunk(ks, vst, pw, qg, o, mr0, mr1, l0, l1, ci * 64, m0, g, tig);

    float inv0 = 1.0f / l0, inv1 = 1.0f / l1;
    float* ob = out + ((size_t)b * TT + m0) * HH;
#pragma unroll
    for (int nt = 0; nt < 8; nt++) {
        int cb = nt * 8 + 2 * tig;
        *(float2*)(ob + g * 64 + cb) = make_float2(o[nt][0] * inv0, o[nt][1] * inv0);
        *(float2*)(ob + (8 + g) * 64 + cb) = make_float2(o[nt][2] * inv1, o[nt][3] * inv1);
    }
}

extern "C" void kernel_launch(void* const* d_in, const int* in_sizes, int n_in,
                              void* d_out, int out_size)
{
    (void)in_sizes; (void)n_in; (void)out_size;
    const float* x  = (const float*)d_in[0];
    const float* Wq = (const float*)d_in[1];
    const float* Wk = (const float*)d_in[2];
    const float* Wv = (const float*)d_in[3];
    float* out = (float*)d_out;

    const int qkv_smem = 2 * QS_STAGE;                        // ~112 KB
    cudaFuncSetAttribute(qkv_kernel, cudaFuncAttributeMaxDynamicSharedMemorySize, qkv_smem);
    cudaFuncSetAttribute(attn_kernel, cudaFuncAttributeMaxDynamicSharedMemorySize, ATTN_SMEM);

    wt_kernel<<<(3 * HH * EE + 255) / 256, 256>>>(Wq, Wk, Wv);
    qkv_kernel<<<(BB * TT) / 128, 256, qkv_smem>>>(x);
    attn_kernel<<<BB, 512, ATTN_SMEM>>>(out);
}